// round 15
// baseline (speedup 1.0000x reference)
#include <cuda_runtime.h>
#include <math.h>

// ---------------- scratch (static device globals; no allocation) ----------------
__device__ float g_cnn[32768 * 128];     // CNN output per frame
__device__ float g_feats[32768 * 64];    // after FC+BN stack
__device__ float g_xg[32768 * 512];      // precomputed x @ enc_w_ih^T + enc_b
__device__ float g_hdec[10][1024 * 128]; // decoder h history for output head

#define WPAD 132   // weight row pad: 132 % 32 == 4 (conflict-free LDS.128 phases)

__device__ __forceinline__ void fma2(unsigned long long& d,
                                     unsigned long long a, unsigned long long b) {
    asm("fma.rn.f32x2 %0, %1, %2, %0;" : "+l"(d) : "l"(a), "l"(b));
}
__device__ __forceinline__ unsigned long long pack2(float v) {
    unsigned long long r;
    asm("mov.b64 %0, {%1, %1};" : "=l"(r) : "f"(v));
    return r;
}
__device__ __forceinline__ unsigned long long packab(float a, float b) {
    unsigned long long r;
    asm("mov.b64 %0, {%1, %2};" : "=l"(r) : "f"(a), "f"(b));
    return r;
}
__device__ __forceinline__ float ulo(unsigned long long v) {
    return __uint_as_float((unsigned)(v & 0xffffffffull));
}
__device__ __forceinline__ float uhi(unsigned long long v) {
    return __uint_as_float((unsigned)(v >> 32));
}
__device__ __forceinline__ float f2sum(unsigned long long v) { return ulo(v) + uhi(v); }
__device__ __forceinline__ unsigned smem_u32(const void* p) {
    unsigned a;
    asm("{ .reg .u64 t; cvta.to.shared.u64 t, %1; cvt.u32.u64 %0, t; }" : "=r"(a) : "l"(p));
    return a;
}

// ---------------- CNN: persistent, frame-pair packed f32x2 (R10/R12 version) --------
#define FPB 4
#define IRS 50
#define CNN_GRID 592
__global__ void __launch_bounds__(128) cnn_kernel(
    const float* __restrict__ obs,
    const float* __restrict__ w1, const float* __restrict__ b1,
    const float* __restrict__ w2, const float* __restrict__ b2)
{
    __shared__ float s_ini[4 * 12 * IRS];
    __shared__ float s_p1i[16 * 7 * 2 * 16];
    __shared__ float s_w1[576];
    __shared__ float s_b1[16];
    __shared__ float s_w2t[144 * 33];
    __shared__ float s_b2[32];

    int tid = threadIdx.x; // 128
    for (int i = tid; i < 4 * 12 * IRS; i += 128) s_ini[i] = 0.f;
    for (int i = tid; i < 16 * 7 * 2 * 16; i += 128) s_p1i[i] = 0.f;
    for (int i = tid; i < 576; i += 128) s_w1[i] = w1[i];
    if (tid < 16) s_b1[tid] = b1[tid];
    for (int i = tid; i < 4608; i += 128) {
        int oc = i / 144, r = i % 144;
        s_w2t[r * 33 + oc] = w2[i];
    }
    if (tid < 32) s_b2[tid] = b2[tid];
    __syncthreads();

    for (long f0 = (long)blockIdx.x * FPB; f0 < 32768; f0 += (long)gridDim.x * FPB) {
        for (int i = tid; i < FPB * 400; i += 128) {
            int f = i / 400, rem = i % 400;
            int ic = rem / 100, p = rem % 100, y = p / 10, x = p % 10;
            s_ini[(ic * 12 + y + 1) * IRS + (x + 1) * 4 + f] = obs[f0 * 400 + i];
        }
        __syncthreads();

        if (tid < 100) {
            int fp = tid / 50, rem = tid % 50, ocg = rem / 25, pos = rem % 25;
            int py = pos / 5, px = pos % 5;
            unsigned long long acc2[8][4];
#pragma unroll
            for (int o = 0; o < 8; o++) {
                unsigned long long bp = pack2(s_b1[ocg * 8 + o]);
#pragma unroll
                for (int p = 0; p < 4; p++) acc2[o][p] = bp;
            }
#pragma unroll
            for (int ic = 0; ic < 4; ic++) {
                unsigned long long patch2[4][4];
#pragma unroll
                for (int r = 0; r < 4; r++)
#pragma unroll
                    for (int cc = 0; cc < 4; cc++)
                        patch2[r][cc] = *(const unsigned long long*)
                            &s_ini[(ic * 12 + 2 * py + r) * IRS + (2 * px + cc) * 4 + fp * 2];
#pragma unroll
                for (int o = 0; o < 8; o++) {
                    int oc = ocg * 8 + o;
#pragma unroll
                    for (int ky = 0; ky < 3; ky++)
#pragma unroll
                        for (int kx = 0; kx < 3; kx++) {
                            unsigned long long wp = pack2(s_w1[(oc * 4 + ic) * 9 + ky * 3 + kx]);
                            fma2(acc2[o][0], patch2[ky][kx], wp);
                            fma2(acc2[o][1], patch2[ky][kx + 1], wp);
                            fma2(acc2[o][2], patch2[ky + 1][kx], wp);
                            fma2(acc2[o][3], patch2[ky + 1][kx + 1], wp);
                        }
                }
            }
#pragma unroll
            for (int o = 0; o < 8; o++) {
                int oc = ocg * 8 + o;
                float mlo = fmaxf(fmaxf(ulo(acc2[o][0]), ulo(acc2[o][1])),
                                  fmaxf(ulo(acc2[o][2]), ulo(acc2[o][3])));
                float mhi = fmaxf(fmaxf(uhi(acc2[o][0]), uhi(acc2[o][1])),
                                  fmaxf(uhi(acc2[o][2]), uhi(acc2[o][3])));
                unsigned long long pk = packab(fmaxf(mlo, 0.f), fmaxf(mhi, 0.f));
                int idx = ((oc * 7 + py + 1) * 2 + fp) * 16 + (px + 1) * 2;
                *(unsigned long long*)&s_p1i[idx] = pk;
            }
        }
        __syncthreads();

        {
            int half = tid >> 6, fp = (tid >> 5) & 1, oc = tid & 31;
            unsigned long long acc2[2][4];
            unsigned long long bp = pack2(s_b2[oc]);
#pragma unroll
            for (int yl = 0; yl < 2; yl++)
#pragma unroll
                for (int x = 0; x < 4; x++) acc2[yl][x] = bp;

            for (int ic = 0; ic < 16; ic++) {
                unsigned long long in2[4][6];
#pragma unroll
                for (int rl = 0; rl < 4; rl++)
#pragma unroll
                    for (int cp = 0; cp < 3; cp++) {
                        ulonglong2 v = *(const ulonglong2*)
                            &s_p1i[((ic * 7 + 2 * half + rl) * 2 + fp) * 16 + cp * 4];
                        in2[rl][2 * cp] = v.x;
                        in2[rl][2 * cp + 1] = v.y;
                    }
#pragma unroll
                for (int ky = 0; ky < 3; ky++)
#pragma unroll
                    for (int kx = 0; kx < 3; kx++) {
                        unsigned long long wp = pack2(s_w2t[(ic * 9 + ky * 3 + kx) * 33 + oc]);
#pragma unroll
                        for (int yl = 0; yl < 2; yl++)
#pragma unroll
                            for (int x = 0; x < 4; x++)
                                fma2(acc2[yl][x], in2[yl + ky][x + kx], wp);
                    }
            }
#pragma unroll
            for (int px = 0; px < 2; px++) {
                float mlo = fmaxf(fmaxf(ulo(acc2[0][2 * px]), ulo(acc2[0][2 * px + 1])),
                                  fmaxf(ulo(acc2[1][2 * px]), ulo(acc2[1][2 * px + 1])));
                float mhi = fmaxf(fmaxf(uhi(acc2[0][2 * px]), uhi(acc2[0][2 * px + 1])),
                                  fmaxf(uhi(acc2[1][2 * px]), uhi(acc2[1][2 * px + 1])));
                long fr = f0 + fp * 2;
                g_cnn[fr * 128 + oc * 4 + half * 2 + px] = fmaxf(mlo, 0.f);
                g_cnn[(fr + 1) * 128 + oc * 4 + half * 2 + px] = fmaxf(mhi, 0.f);
            }
        }
        __syncthreads();
    }
}

// ---------------- FC stack: persistent; fc1+bn1+relu -> fc2+bn2+relu ----------------
#define FC_GRID 148
__global__ void __launch_bounds__(256) fc_kernel(
    const float* __restrict__ fc1w, const float* __restrict__ fc1b,
    const float* __restrict__ g1, const float* __restrict__ be1,
    const float* __restrict__ m1, const float* __restrict__ v1,
    const float* __restrict__ fc2w, const float* __restrict__ fc2b,
    const float* __restrict__ g2, const float* __restrict__ be2,
    const float* __restrict__ m2, const float* __restrict__ v2)
{
    extern __shared__ float sm[];
    float* w1s = sm;                   // 128 rows x WPAD
    float* w2s = w1s + 128 * WPAD;     // 64 rows x WPAD
    float* xs  = w2s + 64 * WPAD;      // 64 x 128 plain
    float* ms  = xs + 64 * 128;        // 64 x 128 plain

    int tid = threadIdx.x;
    for (int i = tid; i < 128 * 128; i += 256) {
        int row = i >> 7, k = i & 127;
        w1s[row * WPAD + k] = fc1w[i];
    }
    for (int i = tid; i < 64 * 128; i += 256) {
        int row = i >> 7, k = i & 127;
        w2s[row * WPAD + k] = fc2w[i];
    }
    int tj = tid & 31, tr = tid >> 5;
    float s1[4], bb1[4], s2[2], bb2[2];
#pragma unroll
    for (int a = 0; a < 4; a++) {
        int j = tj + 32 * a;
        s1[a] = g1[j] * rsqrtf(v1[j] + 1e-5f);
        bb1[a] = (fc1b[j] - m1[j]) * s1[a] + be1[j];
    }
#pragma unroll
    for (int a = 0; a < 2; a++) {
        int j = tj + 32 * a;
        s2[a] = g2[j] * rsqrtf(v2[j] + 1e-5f);
        bb2[a] = (fc2b[j] - m2[j]) * s2[a] + be2[j];
    }

    for (long t = blockIdx.x; t < 512; t += gridDim.x) {
        long r0 = t * 64;
        for (int i = tid; i < 64 * 128; i += 256) xs[i] = g_cnn[r0 * 128 + i];
        __syncthreads();
        {
            unsigned long long acc2[4][8];
#pragma unroll
            for (int a = 0; a < 4; a++)
#pragma unroll
                for (int b = 0; b < 8; b++) acc2[a][b] = 0ull;
            for (int kk = 0; kk < 32; kk++) {
                ulonglong2 w2v[4], h2v[8];
#pragma unroll
                for (int a = 0; a < 4; a++)
                    w2v[a] = *reinterpret_cast<const ulonglong2*>(&w1s[(tj + 32 * a) * WPAD + (kk << 2)]);
#pragma unroll
                for (int b = 0; b < 8; b++)
                    h2v[b] = *reinterpret_cast<const ulonglong2*>(&xs[(tr * 8 + b) * 128 + (kk << 2)]);
#pragma unroll
                for (int a = 0; a < 4; a++)
#pragma unroll
                    for (int b = 0; b < 8; b++) {
                        fma2(acc2[a][b], w2v[a].x, h2v[b].x);
                        fma2(acc2[a][b], w2v[a].y, h2v[b].y);
                    }
            }
#pragma unroll
            for (int a = 0; a < 4; a++) {
                int j = tj + 32 * a;
#pragma unroll
                for (int b = 0; b < 8; b++)
                    ms[(tr * 8 + b) * 128 + j] = fmaxf(f2sum(acc2[a][b]) * s1[a] + bb1[a], 0.f);
            }
        }
        __syncthreads();
        {
            unsigned long long acc2[2][8];
#pragma unroll
            for (int a = 0; a < 2; a++)
#pragma unroll
                for (int b = 0; b < 8; b++) acc2[a][b] = 0ull;
            for (int kk = 0; kk < 32; kk++) {
                ulonglong2 w2v[2], h2v[8];
#pragma unroll
                for (int a = 0; a < 2; a++)
                    w2v[a] = *reinterpret_cast<const ulonglong2*>(&w2s[(tj + 32 * a) * WPAD + (kk << 2)]);
#pragma unroll
                for (int b = 0; b < 8; b++)
                    h2v[b] = *reinterpret_cast<const ulonglong2*>(&ms[(tr * 8 + b) * 128 + (kk << 2)]);
#pragma unroll
                for (int a = 0; a < 2; a++)
#pragma unroll
                    for (int b = 0; b < 8; b++) {
                        fma2(acc2[a][b], w2v[a].x, h2v[b].x);
                        fma2(acc2[a][b], w2v[a].y, h2v[b].y);
                    }
            }
#pragma unroll
            for (int a = 0; a < 2; a++) {
                int j = tj + 32 * a;
#pragma unroll
                for (int b = 0; b < 8; b++)
                    g_feats[(r0 + tr * 8 + b) * 64 + j] = fmaxf(f2sum(acc2[a][b]) * s2[a] + bb2[a], 0.f);
            }
        }
        __syncthreads();
    }
}

// ---------------- encoder x-projection GEMM: persistent, j-panel staged once --------
#define BPAD 68   // 68 % 32 == 4
#define XP_GROUPS 74
__global__ void __launch_bounds__(512) xproj_kernel(const float* __restrict__ wih,
                                                    const float* __restrict__ eb)
{
    extern __shared__ float sm[];
    float* As = sm;               // [128][64] plain (m-major)
    float* Bs = sm + 128 * 64;    // [128][BPAD] (j-major, padded)

    int tid = threadIdx.x;
    int j0 = (blockIdx.x & 3) * 128;
    int grp = blockIdx.x >> 2;

    for (int i = tid; i < 128 * 64; i += 512) {
        int j = i >> 6, k = i & 63;
        Bs[j * BPAD + k] = wih[(long)(j0 + j) * 64 + k];
    }

    int tx = tid & 15, ty = tid >> 4;
    int m0 = ty * 4;
    float ebv[8];
#pragma unroll
    for (int j = 0; j < 8; j++) ebv[j] = eb[j0 + tx + 16 * j];

    for (int t = grp; t < 256; t += XP_GROUPS) {
        long r0 = (long)t * 128;
        for (int i = tid; i < 128 * 64; i += 512) As[i] = g_feats[r0 * 64 + i];
        __syncthreads();

        unsigned long long acc2[4][8];
#pragma unroll
        for (int i = 0; i < 4; i++)
#pragma unroll
            for (int j = 0; j < 8; j++) acc2[i][j] = 0ull;

        for (int kk = 0; kk < 16; kk++) {
            ulonglong2 a2[4], b2[8];
#pragma unroll
            for (int i = 0; i < 4; i++)
                a2[i] = *reinterpret_cast<const ulonglong2*>(&As[(m0 + i) * 64 + (kk << 2)]);
#pragma unroll
            for (int j = 0; j < 8; j++)
                b2[j] = *reinterpret_cast<const ulonglong2*>(&Bs[(tx + 16 * j) * BPAD + (kk << 2)]);
#pragma unroll
            for (int i = 0; i < 4; i++)
#pragma unroll
                for (int j = 0; j < 8; j++) {
                    fma2(acc2[i][j], a2[i].x, b2[j].x);
                    fma2(acc2[i][j], a2[i].y, b2[j].y);
                }
        }

#pragma unroll
        for (int i = 0; i < 4; i++) {
            long row = (r0 + m0 + i) * 512 + j0;
#pragma unroll
            for (int j = 0; j < 8; j++)
                g_xg[row + tx + 16 * j] = f2sum(acc2[i][j]) + ebv[j];
        }
        __syncthreads();
    }
}

// ---------------- persistent LSTM: clusters of 4, DSMEM h, G2xK2xB4 split ----------
// 16 warps (512 thr). warp w: T = w&3 (8 batch rows T+4j), K = (w>>2)&1 (k half),
// G = w>>3 (gates 2G,2G+1). K0 warps bake xg/bias into acc init. Warps 0-3 (G0K0,
// one per SMSP) do gate math combining 3 partial sets from sred.
// LSU: 16w x 16kk x (8 w-wf + 8 h-wf) = 4096 wf/step == fma floor 4096 cyc.
#define SRP 17
__global__ void __launch_bounds__(512, 1) __cluster_dims__(4, 1, 1)
lstm_persistent(const float* __restrict__ encw, const float* __restrict__ dwi,
                const float* __restrict__ dwh, const float* __restrict__ decb)
{
    extern __shared__ float sm[];
    float* wse = sm;                     // 128 x WPAD encoder slice
    float* wsd = sm + 128 * WPAD;        // 128 x WPAD decoder slice (ih+hh)
    float* hs  = sm + 2 * 128 * WPAD;    // 2 buffers x 32 x 128
    float* sred = hs + 2 * 32 * 128;     // 16*32 x SRP partials

    int tid = threadIdx.x;
    unsigned rank = blockIdx.x & 3;
    int b0 = (blockIdx.x >> 2) * 32;
    int u0 = rank * 32;

    for (int i = tid; i < 128 * 128; i += 512) {
        int row = i >> 7, k = i & 127;
        int grow = ((row >> 5) * 128) + u0 + (row & 31);
        wse[row * WPAD + k] = encw[grow * 128 + k];
        wsd[row * WPAD + k] = dwi[grow * 128 + k] + dwh[grow * 128 + k];
    }
    for (int i = tid; i < 32 * 128; i += 512) hs[i] = 0.f;

    unsigned hs_local = smem_u32(hs);
    unsigned rb[4];
#pragma unroll
    for (int r = 0; r < 4; r++)
        asm("mapa.shared::cluster.u32 %0, %1, %2;" : "=r"(rb[r]) : "r"(hs_local), "r"(r));

    __syncthreads();
    asm volatile("barrier.cluster.arrive.aligned;" ::: "memory");
    asm volatile("barrier.cluster.wait.aligned;" ::: "memory");

    int tj = tid & 31;
    int w  = tid >> 5;          // 0..15
    int T  = w & 3;             // batch group: rows T + 4*jb
    int K  = (w >> 2) & 1;      // k half
    int G  = w >> 3;            // gate pair: gates 2G, 2G+1
    int u = u0 + tj;

    float db2[2];
#pragma unroll
    for (int g = 0; g < 2; g++) db2[g] = decb[(2 * G + g) * 128 + u];

    float c[8] = {0.f, 0.f, 0.f, 0.f, 0.f, 0.f, 0.f, 0.f};  // live only on math warps

    // K0 warps prefetch step-0 gate inputs for their own 2 gates
    float xn[2][8];
    if (K == 0) {
#pragma unroll
        for (int jb = 0; jb < 8; jb++) {
            const float* xr = g_xg + ((long)(b0 + T + 4 * jb) * 32 + 0) * 512;
#pragma unroll
            for (int g = 0; g < 2; g++) xn[g][jb] = xr[(2 * G + g) * 128 + u];
        }
    }

    int kbase = K * 16;
    bool is_math = (w < 4);   // G==0 && K==0
    int pread = 0;
    for (int step = 0; step < 42; step++) {
        const float* ws = (step < 32) ? wse : wsd;
        const float* hsr = hs + pread * (32 * 128);

        unsigned long long acc2[2][8];
        if (K == 0) {
#pragma unroll
            for (int g = 0; g < 2; g++)
#pragma unroll
                for (int jb = 0; jb < 8; jb++) acc2[g][jb] = packab(xn[g][jb], 0.f);
        } else {
#pragma unroll
            for (int g = 0; g < 2; g++)
#pragma unroll
                for (int jb = 0; jb < 8; jb++) acc2[g][jb] = 0ull;
        }

        for (int kk = kbase; kk < kbase + 16; kk++) {
            ulonglong2 w2v[2], h2v[8];
#pragma unroll
            for (int g = 0; g < 2; g++)
                w2v[g] = *reinterpret_cast<const ulonglong2*>(
                    &ws[((2 * G + g) * 32 + tj) * WPAD + (kk << 2)]);
#pragma unroll
            for (int jb = 0; jb < 8; jb++)
                h2v[jb] = *reinterpret_cast<const ulonglong2*>(
                    &hsr[(T + 4 * jb) * 128 + (kk << 2)]);
#pragma unroll
            for (int g = 0; g < 2; g++)
#pragma unroll
                for (int jb = 0; jb < 8; jb++) {
                    fma2(acc2[g][jb], w2v[g].x, h2v[jb].x);
                    fma2(acc2[g][jb], w2v[g].y, h2v[jb].y);
                }
        }

        if (!is_math) {
            float* dst = &sred[(w * 32 + tj) * SRP];
#pragma unroll
            for (int jb = 0; jb < 8; jb++) {
                dst[jb] = f2sum(acc2[0][jb]);
                dst[8 + jb] = f2sum(acc2[1][jb]);
            }
        }
        __syncthreads();

        if (is_math) {
            const float* pA = &sred[((T + 4) * 32 + tj) * SRP];   // G0 K1
            const float* pB = &sred[((T + 8) * 32 + tj) * SRP];   // G1 K0 (xn baked)
            const float* pC = &sred[((T + 12) * 32 + tj) * SRP];  // G1 K1
            unsigned woff = (unsigned)((1 - pread) * (32 * 128 * 4));
#pragma unroll
            for (int jb = 0; jb < 8; jb++) {
                int rloc = T + 4 * jb;
                float gi = f2sum(acc2[0][jb]) + pA[jb];
                float gf = f2sum(acc2[1][jb]) + pA[8 + jb];
                float gg = pB[jb] + pC[jb];
                float go = pB[8 + jb] + pC[8 + jb];
                float si = 1.f / (1.f + __expf(-gi));
                float sf = 1.f / (1.f + __expf(-gf));
                float so = 1.f / (1.f + __expf(-go));
                float tg = tanhf(gg);
                float cn = sf * c[jb] + si * tg;
                c[jb] = cn;
                float hn = so * tanhf(cn);
                if (step < 41) {
                    unsigned eoff = woff + (unsigned)(rloc * 128 + u) * 4u;
#pragma unroll
                    for (int r = 0; r < 4; r++)
                        asm volatile("st.shared::cluster.f32 [%0], %1;"
                                     :: "r"(rb[r] + eoff), "f"(hn) : "memory");
                }
                if (step >= 32) g_hdec[step - 32][(b0 + rloc) * 128 + u] = hn;
            }
        }

        if (step < 41) {
            asm volatile("barrier.cluster.arrive.aligned;" ::: "memory");
            if (K == 0) {
                if (step + 1 < 32) {
#pragma unroll
                    for (int jb = 0; jb < 8; jb++) {
                        const float* xr = g_xg + ((long)(b0 + T + 4 * jb) * 32 + (step + 1)) * 512;
#pragma unroll
                        for (int g = 0; g < 2; g++) xn[g][jb] = xr[(2 * G + g) * 128 + u];
                    }
                } else {
#pragma unroll
                    for (int jb = 0; jb < 8; jb++)
#pragma unroll
                        for (int g = 0; g < 2; g++) xn[g][jb] = db2[g];
                }
            }
            asm volatile("barrier.cluster.wait.aligned;" ::: "memory");
            pread ^= 1;
        }
    }

    asm volatile("barrier.cluster.arrive.aligned;" ::: "memory");
    asm volatile("barrier.cluster.wait.aligned;" ::: "memory");
}

// ---------------- output head ----------------
__global__ void head_kernel(const float* __restrict__ ow, const float* __restrict__ ob,
                            float* __restrict__ out)
{
    __shared__ float hsm[64 * 129];
    __shared__ float wsm[12 * 129];
    __shared__ float bsm[12];
    int tid = threadIdx.x;
    int s = blockIdx.y, b0 = blockIdx.x * 64;
    for (int i = tid; i < 64 * 128; i += 256) {
        int r = i >> 7, k = i & 127;
        hsm[r * 129 + k] = g_hdec[s][(b0 + r) * 128 + k];
    }
    for (int i = tid; i < 12 * 128; i += 256) {
        int r = i / 128, k = i % 128;
        wsm[r * 129 + k] = ow[i];
    }
    if (tid < 12) bsm[tid] = ob[tid];
    __syncthreads();
    for (int it = tid; it < 64 * 12; it += 256) {
        int b = it / 12, v = it % 12;
        float acc = bsm[v];
        for (int k = 0; k < 128; k++) acc += hsm[b * 129 + k] * wsm[v * 129 + k];
        out[(long)(b0 + b) * 120 + s * 12 + v] = acc;
    }
}

// ---------------- launcher ----------------
extern "C" void kernel_launch(void* const* d_in, const int* in_sizes, int n_in,
                              void* d_out, int out_size)
{
    const float* obs    = (const float*)d_in[0];
    const float* c1w    = (const float*)d_in[1];
    const float* c1b    = (const float*)d_in[2];
    const float* c2w    = (const float*)d_in[3];
    const float* c2b    = (const float*)d_in[4];
    const float* fc1w   = (const float*)d_in[5];
    const float* fc1b   = (const float*)d_in[6];
    const float* bn1g   = (const float*)d_in[7];
    const float* bn1b   = (const float*)d_in[8];
    const float* bn1m   = (const float*)d_in[9];
    const float* bn1v   = (const float*)d_in[10];
    const float* fc2w   = (const float*)d_in[11];
    const float* fc2b   = (const float*)d_in[12];
    const float* bn2g   = (const float*)d_in[13];
    const float* bn2b   = (const float*)d_in[14];
    const float* bn2m   = (const float*)d_in[15];
    const float* bn2v   = (const float*)d_in[16];
    const float* encwih = (const float*)d_in[17];
    const float* encwhh = (const float*)d_in[18];
    const float* encb   = (const float*)d_in[19];
    const float* decwih = (const float*)d_in[20];
    const float* decwhh = (const float*)d_in[21];
    const float* decb   = (const float*)d_in[22];
    const float* outw   = (const float*)d_in[23];
    const float* outb   = (const float*)d_in[24];
    float* out = (float*)d_out;

    const int fc_smem    = (128 * WPAD + 64 * WPAD + 64 * 128 * 2) * 4;
    const int xproj_smem = (128 * 64 + 128 * BPAD) * 4;
    const int lstm_smem  = (2 * 128 * WPAD + 2 * 32 * 128 + 16 * 32 * SRP) * 4; // ~198 KB
    cudaFuncSetAttribute(fc_kernel, cudaFuncAttributeMaxDynamicSharedMemorySize, fc_smem);
    cudaFuncSetAttribute(xproj_kernel, cudaFuncAttributeMaxDynamicSharedMemorySize, xproj_smem);
    cudaFuncSetAttribute(lstm_persistent, cudaFuncAttributeMaxDynamicSharedMemorySize, lstm_smem);

    cnn_kernel<<<CNN_GRID, 128>>>(obs, c1w, c1b, c2w, c2b);
    fc_kernel<<<FC_GRID, 256, fc_smem>>>(fc1w, fc1b, bn1g, bn1b, bn1m, bn1v,
                                         fc2w, fc2b, bn2g, bn2b, bn2m, bn2v);
    xproj_kernel<<<XP_GROUPS * 4, 512, xproj_smem>>>(encwih, encb);

    lstm_persistent<<<128, 512, lstm_smem>>>(encwhh, decwih, decwhh, decb);

    dim3 hgrid(16, 10);
    head_kernel<<<hgrid, 256>>>(outw, outb, out);
}

// round 16
// speedup vs baseline: 1.0950x; 1.0950x over previous
#include <cuda_runtime.h>
#include <math.h>

// ---------------- scratch (static device globals; no allocation) ----------------
__device__ float g_cnn[32768 * 128];     // CNN output per frame
__device__ float g_feats[32768 * 64];    // after FC+BN stack
__device__ float g_xg[32768 * 512];      // precomputed x @ enc_w_ih^T + enc_b
__device__ float g_hdec[10][1024 * 128]; // decoder h history for output head

#define WPAD 132   // weight row pad: 132 % 32 == 4 (conflict-free LDS.128 phases)

__device__ __forceinline__ void fma2(unsigned long long& d,
                                     unsigned long long a, unsigned long long b) {
    asm("fma.rn.f32x2 %0, %1, %2, %0;" : "+l"(d) : "l"(a), "l"(b));
}
__device__ __forceinline__ unsigned long long pack2(float v) {
    unsigned long long r;
    asm("mov.b64 %0, {%1, %1};" : "=l"(r) : "f"(v));
    return r;
}
__device__ __forceinline__ unsigned long long packab(float a, float b) {
    unsigned long long r;
    asm("mov.b64 %0, {%1, %2};" : "=l"(r) : "f"(a), "f"(b));
    return r;
}
__device__ __forceinline__ float ulo(unsigned long long v) {
    return __uint_as_float((unsigned)(v & 0xffffffffull));
}
__device__ __forceinline__ float uhi(unsigned long long v) {
    return __uint_as_float((unsigned)(v >> 32));
}
__device__ __forceinline__ float f2sum(unsigned long long v) { return ulo(v) + uhi(v); }
__device__ __forceinline__ unsigned smem_u32(const void* p) {
    unsigned a;
    asm("{ .reg .u64 t; cvta.to.shared.u64 t, %1; cvt.u32.u64 %0, t; }" : "=r"(a) : "l"(p));
    return a;
}

// ---------------- CNN: persistent, frame-pair packed f32x2 (R10 best) ----------------
#define FPB 4
#define IRS 50
#define CNN_GRID 592
__global__ void __launch_bounds__(128) cnn_kernel(
    const float* __restrict__ obs,
    const float* __restrict__ w1, const float* __restrict__ b1,
    const float* __restrict__ w2, const float* __restrict__ b2)
{
    __shared__ float s_ini[4 * 12 * IRS];
    __shared__ float s_p1i[16 * 7 * 2 * 16];
    __shared__ float s_w1[576];
    __shared__ float s_b1[16];
    __shared__ float s_w2t[144 * 33];
    __shared__ float s_b2[32];

    int tid = threadIdx.x; // 128
    for (int i = tid; i < 4 * 12 * IRS; i += 128) s_ini[i] = 0.f;
    for (int i = tid; i < 16 * 7 * 2 * 16; i += 128) s_p1i[i] = 0.f;
    for (int i = tid; i < 576; i += 128) s_w1[i] = w1[i];
    if (tid < 16) s_b1[tid] = b1[tid];
    for (int i = tid; i < 4608; i += 128) {
        int oc = i / 144, r = i % 144;
        s_w2t[r * 33 + oc] = w2[i];
    }
    if (tid < 32) s_b2[tid] = b2[tid];
    __syncthreads();

    for (long f0 = (long)blockIdx.x * FPB; f0 < 32768; f0 += (long)gridDim.x * FPB) {
        for (int i = tid; i < FPB * 400; i += 128) {
            int f = i / 400, rem = i % 400;
            int ic = rem / 100, p = rem % 100, y = p / 10, x = p % 10;
            s_ini[(ic * 12 + y + 1) * IRS + (x + 1) * 4 + f] = obs[f0 * 400 + i];
        }
        __syncthreads();

        if (tid < 100) {
            int fp = tid / 50, rem = tid % 50, ocg = rem / 25, pos = rem % 25;
            int py = pos / 5, px = pos % 5;
            unsigned long long acc2[8][4];
#pragma unroll
            for (int o = 0; o < 8; o++) {
                unsigned long long bp = pack2(s_b1[ocg * 8 + o]);
#pragma unroll
                for (int p = 0; p < 4; p++) acc2[o][p] = bp;
            }
#pragma unroll
            for (int ic = 0; ic < 4; ic++) {
                unsigned long long patch2[4][4];
#pragma unroll
                for (int r = 0; r < 4; r++)
#pragma unroll
                    for (int cc = 0; cc < 4; cc++)
                        patch2[r][cc] = *(const unsigned long long*)
                            &s_ini[(ic * 12 + 2 * py + r) * IRS + (2 * px + cc) * 4 + fp * 2];
#pragma unroll
                for (int o = 0; o < 8; o++) {
                    int oc = ocg * 8 + o;
#pragma unroll
                    for (int ky = 0; ky < 3; ky++)
#pragma unroll
                        for (int kx = 0; kx < 3; kx++) {
                            unsigned long long wp = pack2(s_w1[(oc * 4 + ic) * 9 + ky * 3 + kx]);
                            fma2(acc2[o][0], patch2[ky][kx], wp);
                            fma2(acc2[o][1], patch2[ky][kx + 1], wp);
                            fma2(acc2[o][2], patch2[ky + 1][kx], wp);
                            fma2(acc2[o][3], patch2[ky + 1][kx + 1], wp);
                        }
                }
            }
#pragma unroll
            for (int o = 0; o < 8; o++) {
                int oc = ocg * 8 + o;
                float mlo = fmaxf(fmaxf(ulo(acc2[o][0]), ulo(acc2[o][1])),
                                  fmaxf(ulo(acc2[o][2]), ulo(acc2[o][3])));
                float mhi = fmaxf(fmaxf(uhi(acc2[o][0]), uhi(acc2[o][1])),
                                  fmaxf(uhi(acc2[o][2]), uhi(acc2[o][3])));
                unsigned long long pk = packab(fmaxf(mlo, 0.f), fmaxf(mhi, 0.f));
                int idx = ((oc * 7 + py + 1) * 2 + fp) * 16 + (px + 1) * 2;
                *(unsigned long long*)&s_p1i[idx] = pk;
            }
        }
        __syncthreads();

        {
            int half = tid >> 6, fp = (tid >> 5) & 1, oc = tid & 31;
            unsigned long long acc2[2][4];
            unsigned long long bp = pack2(s_b2[oc]);
#pragma unroll
            for (int yl = 0; yl < 2; yl++)
#pragma unroll
                for (int x = 0; x < 4; x++) acc2[yl][x] = bp;

            for (int ic = 0; ic < 16; ic++) {
                unsigned long long in2[4][6];
#pragma unroll
                for (int rl = 0; rl < 4; rl++)
#pragma unroll
                    for (int cp = 0; cp < 3; cp++) {
                        ulonglong2 v = *(const ulonglong2*)
                            &s_p1i[((ic * 7 + 2 * half + rl) * 2 + fp) * 16 + cp * 4];
                        in2[rl][2 * cp] = v.x;
                        in2[rl][2 * cp + 1] = v.y;
                    }
#pragma unroll
                for (int ky = 0; ky < 3; ky++)
#pragma unroll
                    for (int kx = 0; kx < 3; kx++) {
                        unsigned long long wp = pack2(s_w2t[(ic * 9 + ky * 3 + kx) * 33 + oc]);
#pragma unroll
                        for (int yl = 0; yl < 2; yl++)
#pragma unroll
                            for (int x = 0; x < 4; x++)
                                fma2(acc2[yl][x], in2[yl + ky][x + kx], wp);
                    }
            }
#pragma unroll
            for (int px = 0; px < 2; px++) {
                float mlo = fmaxf(fmaxf(ulo(acc2[0][2 * px]), ulo(acc2[0][2 * px + 1])),
                                  fmaxf(ulo(acc2[1][2 * px]), ulo(acc2[1][2 * px + 1])));
                float mhi = fmaxf(fmaxf(uhi(acc2[0][2 * px]), uhi(acc2[0][2 * px + 1])),
                                  fmaxf(uhi(acc2[1][2 * px]), uhi(acc2[1][2 * px + 1])));
                long fr = f0 + fp * 2;
                g_cnn[fr * 128 + oc * 4 + half * 2 + px] = fmaxf(mlo, 0.f);
                g_cnn[(fr + 1) * 128 + oc * 4 + half * 2 + px] = fmaxf(mhi, 0.f);
            }
        }
        __syncthreads();
    }
}

// ---------------- FC stack: persistent; fc1+bn1+relu -> fc2+bn2+relu ----------------
#define FC_GRID 148
__global__ void __launch_bounds__(256) fc_kernel(
    const float* __restrict__ fc1w, const float* __restrict__ fc1b,
    const float* __restrict__ g1, const float* __restrict__ be1,
    const float* __restrict__ m1, const float* __restrict__ v1,
    const float* __restrict__ fc2w, const float* __restrict__ fc2b,
    const float* __restrict__ g2, const float* __restrict__ be2,
    const float* __restrict__ m2, const float* __restrict__ v2)
{
    extern __shared__ float sm[];
    float* w1s = sm;                   // 128 rows x WPAD
    float* w2s = w1s + 128 * WPAD;     // 64 rows x WPAD
    float* xs  = w2s + 64 * WPAD;      // 64 x 128 plain
    float* ms  = xs + 64 * 128;        // 64 x 128 plain

    int tid = threadIdx.x;
    for (int i = tid; i < 128 * 128; i += 256) {
        int row = i >> 7, k = i & 127;
        w1s[row * WPAD + k] = fc1w[i];
    }
    for (int i = tid; i < 64 * 128; i += 256) {
        int row = i >> 7, k = i & 127;
        w2s[row * WPAD + k] = fc2w[i];
    }
    int tj = tid & 31, tr = tid >> 5;
    float s1[4], bb1[4], s2[2], bb2[2];
#pragma unroll
    for (int a = 0; a < 4; a++) {
        int j = tj + 32 * a;
        s1[a] = g1[j] * rsqrtf(v1[j] + 1e-5f);
        bb1[a] = (fc1b[j] - m1[j]) * s1[a] + be1[j];
    }
#pragma unroll
    for (int a = 0; a < 2; a++) {
        int j = tj + 32 * a;
        s2[a] = g2[j] * rsqrtf(v2[j] + 1e-5f);
        bb2[a] = (fc2b[j] - m2[j]) * s2[a] + be2[j];
    }

    for (long t = blockIdx.x; t < 512; t += gridDim.x) {
        long r0 = t * 64;
        for (int i = tid; i < 64 * 128; i += 256) xs[i] = g_cnn[r0 * 128 + i];
        __syncthreads();
        {
            unsigned long long acc2[4][8];
#pragma unroll
            for (int a = 0; a < 4; a++)
#pragma unroll
                for (int b = 0; b < 8; b++) acc2[a][b] = 0ull;
            for (int kk = 0; kk < 32; kk++) {
                ulonglong2 w2v[4], h2v[8];
#pragma unroll
                for (int a = 0; a < 4; a++)
                    w2v[a] = *reinterpret_cast<const ulonglong2*>(&w1s[(tj + 32 * a) * WPAD + (kk << 2)]);
#pragma unroll
                for (int b = 0; b < 8; b++)
                    h2v[b] = *reinterpret_cast<const ulonglong2*>(&xs[(tr * 8 + b) * 128 + (kk << 2)]);
#pragma unroll
                for (int a = 0; a < 4; a++)
#pragma unroll
                    for (int b = 0; b < 8; b++) {
                        fma2(acc2[a][b], w2v[a].x, h2v[b].x);
                        fma2(acc2[a][b], w2v[a].y, h2v[b].y);
                    }
            }
#pragma unroll
            for (int a = 0; a < 4; a++) {
                int j = tj + 32 * a;
#pragma unroll
                for (int b = 0; b < 8; b++)
                    ms[(tr * 8 + b) * 128 + j] = fmaxf(f2sum(acc2[a][b]) * s1[a] + bb1[a], 0.f);
            }
        }
        __syncthreads();
        {
            unsigned long long acc2[2][8];
#pragma unroll
            for (int a = 0; a < 2; a++)
#pragma unroll
                for (int b = 0; b < 8; b++) acc2[a][b] = 0ull;
            for (int kk = 0; kk < 32; kk++) {
                ulonglong2 w2v[2], h2v[8];
#pragma unroll
                for (int a = 0; a < 2; a++)
                    w2v[a] = *reinterpret_cast<const ulonglong2*>(&w2s[(tj + 32 * a) * WPAD + (kk << 2)]);
#pragma unroll
                for (int b = 0; b < 8; b++)
                    h2v[b] = *reinterpret_cast<const ulonglong2*>(&ms[(tr * 8 + b) * 128 + (kk << 2)]);
#pragma unroll
                for (int a = 0; a < 2; a++)
#pragma unroll
                    for (int b = 0; b < 8; b++) {
                        fma2(acc2[a][b], w2v[a].x, h2v[b].x);
                        fma2(acc2[a][b], w2v[a].y, h2v[b].y);
                    }
            }
#pragma unroll
            for (int a = 0; a < 2; a++) {
                int j = tj + 32 * a;
#pragma unroll
                for (int b = 0; b < 8; b++)
                    g_feats[(r0 + tr * 8 + b) * 64 + j] = fmaxf(f2sum(acc2[a][b]) * s2[a] + bb2[a], 0.f);
            }
        }
        __syncthreads();
    }
}

// ---------------- encoder x-projection GEMM: persistent, j-panel staged once --------
#define BPAD 68   // 68 % 32 == 4
#define XP_GROUPS 74
__global__ void __launch_bounds__(512) xproj_kernel(const float* __restrict__ wih,
                                                    const float* __restrict__ eb)
{
    extern __shared__ float sm[];
    float* As = sm;               // [128][64] plain (m-major)
    float* Bs = sm + 128 * 64;    // [128][BPAD] (j-major, padded)

    int tid = threadIdx.x;
    int j0 = (blockIdx.x & 3) * 128;
    int grp = blockIdx.x >> 2;

    for (int i = tid; i < 128 * 64; i += 512) {
        int j = i >> 6, k = i & 63;
        Bs[j * BPAD + k] = wih[(long)(j0 + j) * 64 + k];
    }

    int tx = tid & 15, ty = tid >> 4;
    int m0 = ty * 4;
    float ebv[8];
#pragma unroll
    for (int j = 0; j < 8; j++) ebv[j] = eb[j0 + tx + 16 * j];

    for (int t = grp; t < 256; t += XP_GROUPS) {
        long r0 = (long)t * 128;
        for (int i = tid; i < 128 * 64; i += 512) As[i] = g_feats[r0 * 64 + i];
        __syncthreads();

        unsigned long long acc2[4][8];
#pragma unroll
        for (int i = 0; i < 4; i++)
#pragma unroll
            for (int j = 0; j < 8; j++) acc2[i][j] = 0ull;

        for (int kk = 0; kk < 16; kk++) {
            ulonglong2 a2[4], b2[8];
#pragma unroll
            for (int i = 0; i < 4; i++)
                a2[i] = *reinterpret_cast<const ulonglong2*>(&As[(m0 + i) * 64 + (kk << 2)]);
#pragma unroll
            for (int j = 0; j < 8; j++)
                b2[j] = *reinterpret_cast<const ulonglong2*>(&Bs[(tx + 16 * j) * BPAD + (kk << 2)]);
#pragma unroll
            for (int i = 0; i < 4; i++)
#pragma unroll
                for (int j = 0; j < 8; j++) {
                    fma2(acc2[i][j], a2[i].x, b2[j].x);
                    fma2(acc2[i][j], a2[i].y, b2[j].y);
                }
        }

#pragma unroll
        for (int i = 0; i < 4; i++) {
            long row = (r0 + m0 + i) * 512 + j0;
#pragma unroll
            for (int j = 0; j < 8; j++)
                g_xg[row + tx + 16 * j] = f2sum(acc2[i][j]) + ebv[j];
        }
        __syncthreads();
    }
}

// ---------------- persistent LSTM: clusters of 4, DSMEM h, k-split 16 warps ----------
#define SRSTRIDE 17
__global__ void __launch_bounds__(512, 1) __cluster_dims__(4, 1, 1)
lstm_persistent(const float* __restrict__ encw, const float* __restrict__ dwi,
                const float* __restrict__ dwh, const float* __restrict__ decb)
{
    extern __shared__ float sm[];
    float* wse = sm;                     // 128 rows x WPAD encoder slice
    float* wsd = sm + 128 * WPAD;        // 128 rows x WPAD decoder slice (ih+hh)
    float* hs  = sm + 2 * 128 * WPAD;    // 2 buffers x 32 x 128
    float* sred = hs + 2 * 32 * 128;     // 256 x SRSTRIDE reduce pad

    int tid = threadIdx.x;
    unsigned rank = blockIdx.x & 3;
    int b0 = (blockIdx.x >> 2) * 32;
    int u0 = rank * 32;

    for (int i = tid; i < 128 * 128; i += 512) {
        int row = i >> 7, k = i & 127;
        int grow = ((row >> 5) * 128) + u0 + (row & 31);
        wse[row * WPAD + k] = encw[grow * 128 + k];
        wsd[row * WPAD + k] = dwi[grow * 128 + k] + dwh[grow * 128 + k];
    }
    for (int i = tid; i < 32 * 128; i += 512) hs[i] = 0.f;

    unsigned hs_local = smem_u32(hs);
    unsigned rb[4];
#pragma unroll
    for (int r = 0; r < 4; r++)
        asm("mapa.shared::cluster.u32 %0, %1, %2;" : "=r"(rb[r]) : "r"(hs_local), "r"(r));

    __syncthreads();
    asm volatile("barrier.cluster.arrive.aligned;" ::: "memory");
    asm volatile("barrier.cluster.wait.aligned;" ::: "memory");

    int tj = tid & 31;
    int w  = tid >> 5;          // 0..15
    int kh = w >> 3;            // 0 = k-low half, 1 = k-high half
    int tr = w & 7;             // batch rows tr + 8*b
    int u = u0 + tj;
    float db[4];
#pragma unroll
    for (int a = 0; a < 4; a++) db[a] = decb[a * 128 + u];

    float c[4] = {0.f, 0.f, 0.f, 0.f};

    float xn[4][4];
    if (kh == 0) {
#pragma unroll
        for (int b = 0; b < 4; b++) {
            const float* xr = g_xg + ((long)(b0 + tr + 8 * b) * 32 + 0) * 512;
#pragma unroll
            for (int a = 0; a < 4; a++) xn[b][a] = xr[a * 128 + u];
        }
    }

    int kbase = kh * 16;
    int pread = 0;
    for (int step = 0; step < 42; step++) {
        const float* ws = (step < 32) ? wse : wsd;
        const float* hsr = hs + pread * (32 * 128);

        unsigned long long acc2[4][4];
#pragma unroll
        for (int a = 0; a < 4; a++)
#pragma unroll
            for (int b = 0; b < 4; b++) acc2[a][b] = 0ull;

        for (int kk = kbase; kk < kbase + 16; kk++) {
            ulonglong2 w2v[4], h2v[4];
#pragma unroll
            for (int a = 0; a < 4; a++)
                w2v[a] = *reinterpret_cast<const ulonglong2*>(&ws[(a * 32 + tj) * WPAD + (kk << 2)]);
#pragma unroll
            for (int b = 0; b < 4; b++)
                h2v[b] = *reinterpret_cast<const ulonglong2*>(&hsr[(tr + 8 * b) * 128 + (kk << 2)]);
#pragma unroll
            for (int a = 0; a < 4; a++)
#pragma unroll
                for (int b = 0; b < 4; b++) {
                    fma2(acc2[a][b], w2v[a].x, h2v[b].x);
                    fma2(acc2[a][b], w2v[a].y, h2v[b].y);
                }
        }

        if (kh == 1) {
            float* dst = sred + (tid - 256) * SRSTRIDE;
#pragma unroll
            for (int a = 0; a < 4; a++)
#pragma unroll
                for (int b = 0; b < 4; b++) dst[a * 4 + b] = f2sum(acc2[a][b]);
        }
        __syncthreads();

        if (kh == 0) {
            const float* src = sred + tid * SRSTRIDE;
            unsigned woff = (unsigned)((1 - pread) * (32 * 128 * 4));
#pragma unroll
            for (int b = 0; b < 4; b++) {
                int rloc = tr + 8 * b;
                float gi = f2sum(acc2[0][b]) + src[0 * 4 + b] + xn[b][0];
                float gf = f2sum(acc2[1][b]) + src[1 * 4 + b] + xn[b][1];
                float gg = f2sum(acc2[2][b]) + src[2 * 4 + b] + xn[b][2];
                float go = f2sum(acc2[3][b]) + src[3 * 4 + b] + xn[b][3];
                float si = 1.f / (1.f + __expf(-gi));
                float sf = 1.f / (1.f + __expf(-gf));
                float so = 1.f / (1.f + __expf(-go));
                float tg = tanhf(gg);
                float cn = sf * c[b] + si * tg;
                c[b] = cn;
                float hn = so * tanhf(cn);
                if (step < 41) {
                    unsigned eoff = woff + (unsigned)(rloc * 128 + u) * 4u;
#pragma unroll
                    for (int r = 0; r < 4; r++)
                        asm volatile("st.shared::cluster.f32 [%0], %1;"
                                     :: "r"(rb[r] + eoff), "f"(hn) : "memory");
                }
                if (step >= 32) g_hdec[step - 32][(b0 + rloc) * 128 + u] = hn;
            }
        }

        if (step < 41) {
            asm volatile("barrier.cluster.arrive.aligned;" ::: "memory");
            if (kh == 0) {
                if (step + 1 < 32) {
#pragma unroll
                    for (int b = 0; b < 4; b++) {
                        const float* xr = g_xg + ((long)(b0 + tr + 8 * b) * 32 + (step + 1)) * 512;
#pragma unroll
                        for (int a = 0; a < 4; a++) xn[b][a] = xr[a * 128 + u];
                    }
                } else {
#pragma unroll
                    for (int b = 0; b < 4; b++)
#pragma unroll
                        for (int a = 0; a < 4; a++) xn[b][a] = db[a];
                }
            }
            asm volatile("barrier.cluster.wait.aligned;" ::: "memory");
            pread ^= 1;
        }
    }

    asm volatile("barrier.cluster.arrive.aligned;" ::: "memory");
    asm volatile("barrier.cluster.wait.aligned;" ::: "memory");
}

// ---------------- output head v2: f32x2, k-split 4, transposed w pairs ----------------
// grid (16,10), 256 thr: tid = kseg*64 + b. Per thread: 16 kk-pairs x 12 fma2,
// 1 LDS.64 h-load per kk (w pairs are warp-uniform broadcasts). Pad-13 reduce.
#define HPAD 130
__global__ void __launch_bounds__(256) head_kernel(
    const float* __restrict__ ow, const float* __restrict__ ob,
    float* __restrict__ out)
{
    extern __shared__ float hm[];
    float* hsm = hm;                  // 64 x HPAD
    float* wt2 = hsm + 64 * HPAD;     // 64 kk x 12 v x 2 floats (u64 pairs)
    float* red = wt2 + 64 * 12 * 2;   // 4 x 64 x 13

    int tid = threadIdx.x;
    int s = blockIdx.y, b0 = blockIdx.x * 64;
    for (int i = tid; i < 64 * 128; i += 256) {
        int r = i >> 7, k = i & 127;
        hsm[r * HPAD + k] = g_hdec[s][(b0 + r) * 128 + k];
    }
    for (int i = tid; i < 64 * 12; i += 256) {
        int kk = i / 12, v = i % 12;
        wt2[i * 2]     = ow[v * 128 + 2 * kk];
        wt2[i * 2 + 1] = ow[v * 128 + 2 * kk + 1];
    }
    __syncthreads();

    int b = tid & 63, kseg = tid >> 6;   // kseg 0..3 -> kk in [kseg*16, +16)
    unsigned long long acc[12];
#pragma unroll
    for (int v = 0; v < 12; v++) acc[v] = 0ull;

    for (int kk = kseg * 16; kk < kseg * 16 + 16; kk++) {
        unsigned long long h2 = *(const unsigned long long*)&hsm[b * HPAD + (kk << 1)];
        const unsigned long long* wp = (const unsigned long long*)&wt2[kk * 24];
#pragma unroll
        for (int v = 0; v < 12; v++) fma2(acc[v], h2, wp[v]);
    }
    {
        float* dst = &red[(kseg * 64 + b) * 13];
#pragma unroll
        for (int v = 0; v < 12; v++) dst[v] = f2sum(acc[v]);
    }
    __syncthreads();

    for (int it = tid; it < 64 * 12; it += 256) {
        int b2 = it / 12, v = it % 12;
        float r = red[(0 * 64 + b2) * 13 + v] + red[(1 * 64 + b2) * 13 + v]
                + red[(2 * 64 + b2) * 13 + v] + red[(3 * 64 + b2) * 13 + v] + ob[v];
        out[(long)(b0 + b2) * 120 + s * 12 + v] = r;
    }
}

// ---------------- launcher ----------------
extern "C" void kernel_launch(void* const* d_in, const int* in_sizes, int n_in,
                              void* d_out, int out_size)
{
    const float* obs    = (const float*)d_in[0];
    const float* c1w    = (const float*)d_in[1];
    const float* c1b    = (const float*)d_in[2];
    const float* c2w    = (const float*)d_in[3];
    const float* c2b    = (const float*)d_in[4];
    const float* fc1w   = (const float*)d_in[5];
    const float* fc1b   = (const float*)d_in[6];
    const float* bn1g   = (const float*)d_in[7];
    const float* bn1b   = (const float*)d_in[8];
    const float* bn1m   = (const float*)d_in[9];
    const float* bn1v   = (const float*)d_in[10];
    const float* fc2w   = (const float*)d_in[11];
    const float* fc2b   = (const float*)d_in[12];
    const float* bn2g   = (const float*)d_in[13];
    const float* bn2b   = (const float*)d_in[14];
    const float* bn2m   = (const float*)d_in[15];
    const float* bn2v   = (const float*)d_in[16];
    const float* encwih = (const float*)d_in[17];
    const float* encwhh = (const float*)d_in[18];
    const float* encb   = (const float*)d_in[19];
    const float* decwih = (const float*)d_in[20];
    const float* decwhh = (const float*)d_in[21];
    const float* decb   = (const float*)d_in[22];
    const float* outw   = (const float*)d_in[23];
    const float* outb   = (const float*)d_in[24];
    float* out = (float*)d_out;

    const int fc_smem    = (128 * WPAD + 64 * WPAD + 64 * 128 * 2) * 4;
    const int xproj_smem = (128 * 64 + 128 * BPAD) * 4;
    const int lstm_smem  = (2 * 128 * WPAD + 2 * 32 * 128 + 256 * SRSTRIDE) * 4;
    const int head_smem  = (64 * HPAD + 64 * 12 * 2 + 4 * 64 * 13) * 4;
    cudaFuncSetAttribute(fc_kernel, cudaFuncAttributeMaxDynamicSharedMemorySize, fc_smem);
    cudaFuncSetAttribute(xproj_kernel, cudaFuncAttributeMaxDynamicSharedMemorySize, xproj_smem);
    cudaFuncSetAttribute(lstm_persistent, cudaFuncAttributeMaxDynamicSharedMemorySize, lstm_smem);
    cudaFuncSetAttribute(head_kernel, cudaFuncAttributeMaxDynamicSharedMemorySize, head_smem);

    cnn_kernel<<<CNN_GRID, 128>>>(obs, c1w, c1b, c2w, c2b);
    fc_kernel<<<FC_GRID, 256, fc_smem>>>(fc1w, fc1b, bn1g, bn1b, bn1m, bn1v,
                                         fc2w, fc2b, bn2g, bn2b, bn2m, bn2v);
    xproj_kernel<<<XP_GROUPS * 4, 512, xproj_smem>>>(encwih, encb);

    lstm_persistent<<<128, 512, lstm_smem>>>(encwhh, decwih, decwhh, decb);

    dim3 hgrid(16, 10);
    head_kernel<<<hgrid, 256, head_smem>>>(outw, outb, out);
}

// round 17
// speedup vs baseline: 1.1038x; 1.0081x over previous
#include <cuda_runtime.h>
#include <math.h>

// ---------------- scratch (static device globals; no allocation) ----------------
__device__ float g_cnn[32768 * 128];     // CNN output per frame
__device__ float g_feats[32768 * 64];    // after FC+BN stack
__device__ float g_xg[32768 * 512];      // precomputed x @ enc_w_ih^T + enc_b
__device__ float g_hdec[10][1024 * 128]; // decoder h history for output head

#define WPAD 132   // weight row pad: 132 % 32 == 4 (conflict-free LDS.128 phases)

__device__ __forceinline__ void fma2(unsigned long long& d,
                                     unsigned long long a, unsigned long long b) {
    asm("fma.rn.f32x2 %0, %1, %2, %0;" : "+l"(d) : "l"(a), "l"(b));
}
__device__ __forceinline__ unsigned long long pack2(float v) {
    unsigned long long r;
    asm("mov.b64 %0, {%1, %1};" : "=l"(r) : "f"(v));
    return r;
}
__device__ __forceinline__ unsigned long long packab(float a, float b) {
    unsigned long long r;
    asm("mov.b64 %0, {%1, %2};" : "=l"(r) : "f"(a), "f"(b));
    return r;
}
__device__ __forceinline__ float ulo(unsigned long long v) {
    return __uint_as_float((unsigned)(v & 0xffffffffull));
}
__device__ __forceinline__ float uhi(unsigned long long v) {
    return __uint_as_float((unsigned)(v >> 32));
}
__device__ __forceinline__ float f2sum(unsigned long long v) { return ulo(v) + uhi(v); }
__device__ __forceinline__ unsigned smem_u32(const void* p) {
    unsigned a;
    asm("{ .reg .u64 t; cvta.to.shared.u64 t, %1; cvt.u32.u64 %0, t; }" : "=r"(a) : "l"(p));
    return a;
}

// ---------------- CNN: persistent, frame-pair packed f32x2 ----------------
// 38.3 KB static smem -> 5 CTAs/SM; grid 740 = 5 x 148 for phase overlap.
#define FPB 4
#define IRS 50
#define CNN_GRID 740
__global__ void __launch_bounds__(128) cnn_kernel(
    const float* __restrict__ obs,
    const float* __restrict__ w1, const float* __restrict__ b1,
    const float* __restrict__ w2, const float* __restrict__ b2)
{
    __shared__ float s_ini[4 * 12 * IRS];
    __shared__ float s_p1i[16 * 7 * 2 * 16];
    __shared__ float s_w1[576];
    __shared__ float s_b1[16];
    __shared__ float s_w2t[144 * 33];
    __shared__ float s_b2[32];

    int tid = threadIdx.x; // 128
    for (int i = tid; i < 4 * 12 * IRS; i += 128) s_ini[i] = 0.f;
    for (int i = tid; i < 16 * 7 * 2 * 16; i += 128) s_p1i[i] = 0.f;
    for (int i = tid; i < 576; i += 128) s_w1[i] = w1[i];
    if (tid < 16) s_b1[tid] = b1[tid];
    for (int i = tid; i < 4608; i += 128) {
        int oc = i / 144, r = i % 144;
        s_w2t[r * 33 + oc] = w2[i];
    }
    if (tid < 32) s_b2[tid] = b2[tid];
    __syncthreads();

    for (long f0 = (long)blockIdx.x * FPB; f0 < 32768; f0 += (long)gridDim.x * FPB) {
        for (int i = tid; i < FPB * 400; i += 128) {
            int f = i / 400, rem = i % 400;
            int ic = rem / 100, p = rem % 100, y = p / 10, x = p % 10;
            s_ini[(ic * 12 + y + 1) * IRS + (x + 1) * 4 + f] = obs[f0 * 400 + i];
        }
        __syncthreads();

        if (tid < 100) {
            int fp = tid / 50, rem = tid % 50, ocg = rem / 25, pos = rem % 25;
            int py = pos / 5, px = pos % 5;
            unsigned long long acc2[8][4];
#pragma unroll
            for (int o = 0; o < 8; o++) {
                unsigned long long bp = pack2(s_b1[ocg * 8 + o]);
#pragma unroll
                for (int p = 0; p < 4; p++) acc2[o][p] = bp;
            }
#pragma unroll
            for (int ic = 0; ic < 4; ic++) {
                unsigned long long patch2[4][4];
#pragma unroll
                for (int r = 0; r < 4; r++)
#pragma unroll
                    for (int cc = 0; cc < 4; cc++)
                        patch2[r][cc] = *(const unsigned long long*)
                            &s_ini[(ic * 12 + 2 * py + r) * IRS + (2 * px + cc) * 4 + fp * 2];
#pragma unroll
                for (int o = 0; o < 8; o++) {
                    int oc = ocg * 8 + o;
#pragma unroll
                    for (int ky = 0; ky < 3; ky++)
#pragma unroll
                        for (int kx = 0; kx < 3; kx++) {
                            unsigned long long wp = pack2(s_w1[(oc * 4 + ic) * 9 + ky * 3 + kx]);
                            fma2(acc2[o][0], patch2[ky][kx], wp);
                            fma2(acc2[o][1], patch2[ky][kx + 1], wp);
                            fma2(acc2[o][2], patch2[ky + 1][kx], wp);
                            fma2(acc2[o][3], patch2[ky + 1][kx + 1], wp);
                        }
                }
            }
#pragma unroll
            for (int o = 0; o < 8; o++) {
                int oc = ocg * 8 + o;
                float mlo = fmaxf(fmaxf(ulo(acc2[o][0]), ulo(acc2[o][1])),
                                  fmaxf(ulo(acc2[o][2]), ulo(acc2[o][3])));
                float mhi = fmaxf(fmaxf(uhi(acc2[o][0]), uhi(acc2[o][1])),
                                  fmaxf(uhi(acc2[o][2]), uhi(acc2[o][3])));
                unsigned long long pk = packab(fmaxf(mlo, 0.f), fmaxf(mhi, 0.f));
                int idx = ((oc * 7 + py + 1) * 2 + fp) * 16 + (px + 1) * 2;
                *(unsigned long long*)&s_p1i[idx] = pk;
            }
        }
        __syncthreads();

        {
            int half = tid >> 6, fp = (tid >> 5) & 1, oc = tid & 31;
            unsigned long long acc2[2][4];
            unsigned long long bp = pack2(s_b2[oc]);
#pragma unroll
            for (int yl = 0; yl < 2; yl++)
#pragma unroll
                for (int x = 0; x < 4; x++) acc2[yl][x] = bp;

            for (int ic = 0; ic < 16; ic++) {
                unsigned long long in2[4][6];
#pragma unroll
                for (int rl = 0; rl < 4; rl++)
#pragma unroll
                    for (int cp = 0; cp < 3; cp++) {
                        ulonglong2 v = *(const ulonglong2*)
                            &s_p1i[((ic * 7 + 2 * half + rl) * 2 + fp) * 16 + cp * 4];
                        in2[rl][2 * cp] = v.x;
                        in2[rl][2 * cp + 1] = v.y;
                    }
#pragma unroll
                for (int ky = 0; ky < 3; ky++)
#pragma unroll
                    for (int kx = 0; kx < 3; kx++) {
                        unsigned long long wp = pack2(s_w2t[(ic * 9 + ky * 3 + kx) * 33 + oc]);
#pragma unroll
                        for (int yl = 0; yl < 2; yl++)
#pragma unroll
                            for (int x = 0; x < 4; x++)
                                fma2(acc2[yl][x], in2[yl + ky][x + kx], wp);
                    }
            }
#pragma unroll
            for (int px = 0; px < 2; px++) {
                float mlo = fmaxf(fmaxf(ulo(acc2[0][2 * px]), ulo(acc2[0][2 * px + 1])),
                                  fmaxf(ulo(acc2[1][2 * px]), ulo(acc2[1][2 * px + 1])));
                float mhi = fmaxf(fmaxf(uhi(acc2[0][2 * px]), uhi(acc2[0][2 * px + 1])),
                                  fmaxf(uhi(acc2[1][2 * px]), uhi(acc2[1][2 * px + 1])));
                long fr = f0 + fp * 2;
                g_cnn[fr * 128 + oc * 4 + half * 2 + px] = fmaxf(mlo, 0.f);
                g_cnn[(fr + 1) * 128 + oc * 4 + half * 2 + px] = fmaxf(mhi, 0.f);
            }
        }
        __syncthreads();
    }
}

// ---------------- FC stack: persistent; fc1+bn1+relu -> fc2+bn2+relu ----------------
#define FC_GRID 148
__global__ void __launch_bounds__(256) fc_kernel(
    const float* __restrict__ fc1w, const float* __restrict__ fc1b,
    const float* __restrict__ g1, const float* __restrict__ be1,
    const float* __restrict__ m1, const float* __restrict__ v1,
    const float* __restrict__ fc2w, const float* __restrict__ fc2b,
    const float* __restrict__ g2, const float* __restrict__ be2,
    const float* __restrict__ m2, const float* __restrict__ v2)
{
    extern __shared__ float sm[];
    float* w1s = sm;                   // 128 rows x WPAD
    float* w2s = w1s + 128 * WPAD;     // 64 rows x WPAD
    float* xs  = w2s + 64 * WPAD;      // 64 x 128 plain
    float* ms  = xs + 64 * 128;        // 64 x 128 plain

    int tid = threadIdx.x;
    for (int i = tid; i < 128 * 128; i += 256) {
        int row = i >> 7, k = i & 127;
        w1s[row * WPAD + k] = fc1w[i];
    }
    for (int i = tid; i < 64 * 128; i += 256) {
        int row = i >> 7, k = i & 127;
        w2s[row * WPAD + k] = fc2w[i];
    }
    int tj = tid & 31, tr = tid >> 5;
    float s1[4], bb1[4], s2[2], bb2[2];
#pragma unroll
    for (int a = 0; a < 4; a++) {
        int j = tj + 32 * a;
        s1[a] = g1[j] * rsqrtf(v1[j] + 1e-5f);
        bb1[a] = (fc1b[j] - m1[j]) * s1[a] + be1[j];
    }
#pragma unroll
    for (int a = 0; a < 2; a++) {
        int j = tj + 32 * a;
        s2[a] = g2[j] * rsqrtf(v2[j] + 1e-5f);
        bb2[a] = (fc2b[j] - m2[j]) * s2[a] + be2[j];
    }

    for (long t = blockIdx.x; t < 512; t += gridDim.x) {
        long r0 = t * 64;
        for (int i = tid; i < 64 * 128; i += 256) xs[i] = g_cnn[r0 * 128 + i];
        __syncthreads();
        {
            unsigned long long acc2[4][8];
#pragma unroll
            for (int a = 0; a < 4; a++)
#pragma unroll
                for (int b = 0; b < 8; b++) acc2[a][b] = 0ull;
            for (int kk = 0; kk < 32; kk++) {
                ulonglong2 w2v[4], h2v[8];
#pragma unroll
                for (int a = 0; a < 4; a++)
                    w2v[a] = *reinterpret_cast<const ulonglong2*>(&w1s[(tj + 32 * a) * WPAD + (kk << 2)]);
#pragma unroll
                for (int b = 0; b < 8; b++)
                    h2v[b] = *reinterpret_cast<const ulonglong2*>(&xs[(tr * 8 + b) * 128 + (kk << 2)]);
#pragma unroll
                for (int a = 0; a < 4; a++)
#pragma unroll
                    for (int b = 0; b < 8; b++) {
                        fma2(acc2[a][b], w2v[a].x, h2v[b].x);
                        fma2(acc2[a][b], w2v[a].y, h2v[b].y);
                    }
            }
#pragma unroll
            for (int a = 0; a < 4; a++) {
                int j = tj + 32 * a;
#pragma unroll
                for (int b = 0; b < 8; b++)
                    ms[(tr * 8 + b) * 128 + j] = fmaxf(f2sum(acc2[a][b]) * s1[a] + bb1[a], 0.f);
            }
        }
        __syncthreads();
        {
            unsigned long long acc2[2][8];
#pragma unroll
            for (int a = 0; a < 2; a++)
#pragma unroll
                for (int b = 0; b < 8; b++) acc2[a][b] = 0ull;
            for (int kk = 0; kk < 32; kk++) {
                ulonglong2 w2v[2], h2v[8];
#pragma unroll
                for (int a = 0; a < 2; a++)
                    w2v[a] = *reinterpret_cast<const ulonglong2*>(&w2s[(tj + 32 * a) * WPAD + (kk << 2)]);
#pragma unroll
                for (int b = 0; b < 8; b++)
                    h2v[b] = *reinterpret_cast<const ulonglong2*>(&ms[(tr * 8 + b) * 128 + (kk << 2)]);
#pragma unroll
                for (int a = 0; a < 2; a++)
#pragma unroll
                    for (int b = 0; b < 8; b++) {
                        fma2(acc2[a][b], w2v[a].x, h2v[b].x);
                        fma2(acc2[a][b], w2v[a].y, h2v[b].y);
                    }
            }
#pragma unroll
            for (int a = 0; a < 2; a++) {
                int j = tj + 32 * a;
#pragma unroll
                for (int b = 0; b < 8; b++)
                    g_feats[(r0 + tr * 8 + b) * 64 + j] = fmaxf(f2sum(acc2[a][b]) * s2[a] + bb2[a], 0.f);
            }
        }
        __syncthreads();
    }
}

// ---------------- encoder x-projection GEMM: persistent, j-panel staged once --------
#define BPAD 68   // 68 % 32 == 4
#define XP_GROUPS 74
__global__ void __launch_bounds__(512) xproj_kernel(const float* __restrict__ wih,
                                                    const float* __restrict__ eb)
{
    extern __shared__ float sm[];
    float* As = sm;               // [128][64] plain (m-major)
    float* Bs = sm + 128 * 64;    // [128][BPAD] (j-major, padded)

    int tid = threadIdx.x;
    int j0 = (blockIdx.x & 3) * 128;
    int grp = blockIdx.x >> 2;

    for (int i = tid; i < 128 * 64; i += 512) {
        int j = i >> 6, k = i & 63;
        Bs[j * BPAD + k] = wih[(long)(j0 + j) * 64 + k];
    }

    int tx = tid & 15, ty = tid >> 4;
    int m0 = ty * 4;
    float ebv[8];
#pragma unroll
    for (int j = 0; j < 8; j++) ebv[j] = eb[j0 + tx + 16 * j];

    for (int t = grp; t < 256; t += XP_GROUPS) {
        long r0 = (long)t * 128;
        for (int i = tid; i < 128 * 64; i += 512) As[i] = g_feats[r0 * 64 + i];
        __syncthreads();

        unsigned long long acc2[4][8];
#pragma unroll
        for (int i = 0; i < 4; i++)
#pragma unroll
            for (int j = 0; j < 8; j++) acc2[i][j] = 0ull;

        for (int kk = 0; kk < 16; kk++) {
            ulonglong2 a2[4], b2[8];
#pragma unroll
            for (int i = 0; i < 4; i++)
                a2[i] = *reinterpret_cast<const ulonglong2*>(&As[(m0 + i) * 64 + (kk << 2)]);
#pragma unroll
            for (int j = 0; j < 8; j++)
                b2[j] = *reinterpret_cast<const ulonglong2*>(&Bs[(tx + 16 * j) * BPAD + (kk << 2)]);
#pragma unroll
            for (int i = 0; i < 4; i++)
#pragma unroll
                for (int j = 0; j < 8; j++) {
                    fma2(acc2[i][j], a2[i].x, b2[j].x);
                    fma2(acc2[i][j], a2[i].y, b2[j].y);
                }
        }

#pragma unroll
        for (int i = 0; i < 4; i++) {
            long row = (r0 + m0 + i) * 512 + j0;
#pragma unroll
            for (int j = 0; j < 8; j++)
                g_xg[row + tx + 16 * j] = f2sum(acc2[i][j]) + ebv[j];
        }
        __syncthreads();
    }
}

// ---------------- persistent LSTM: clusters of 4, DSMEM h, k-split 16 warps ----------
#define SRSTRIDE 17
__global__ void __launch_bounds__(512, 1) __cluster_dims__(4, 1, 1)
lstm_persistent(const float* __restrict__ encw, const float* __restrict__ dwi,
                const float* __restrict__ dwh, const float* __restrict__ decb)
{
    extern __shared__ float sm[];
    float* wse = sm;                     // 128 rows x WPAD encoder slice
    float* wsd = sm + 128 * WPAD;        // 128 rows x WPAD decoder slice (ih+hh)
    float* hs  = sm + 2 * 128 * WPAD;    // 2 buffers x 32 x 128
    float* sred = hs + 2 * 32 * 128;     // 256 x SRSTRIDE reduce pad

    int tid = threadIdx.x;
    unsigned rank = blockIdx.x & 3;
    int b0 = (blockIdx.x >> 2) * 32;
    int u0 = rank * 32;

    for (int i = tid; i < 128 * 128; i += 512) {
        int row = i >> 7, k = i & 127;
        int grow = ((row >> 5) * 128) + u0 + (row & 31);
        wse[row * WPAD + k] = encw[grow * 128 + k];
        wsd[row * WPAD + k] = dwi[grow * 128 + k] + dwh[grow * 128 + k];
    }
    for (int i = tid; i < 32 * 128; i += 512) hs[i] = 0.f;

    unsigned hs_local = smem_u32(hs);
    unsigned rb[4];
#pragma unroll
    for (int r = 0; r < 4; r++)
        asm("mapa.shared::cluster.u32 %0, %1, %2;" : "=r"(rb[r]) : "r"(hs_local), "r"(r));

    __syncthreads();
    asm volatile("barrier.cluster.arrive.aligned;" ::: "memory");
    asm volatile("barrier.cluster.wait.aligned;" ::: "memory");

    int tj = tid & 31;
    int w  = tid >> 5;          // 0..15
    int kh = w >> 3;            // 0 = k-low half, 1 = k-high half
    int tr = w & 7;             // batch rows tr + 8*b
    int u = u0 + tj;
    float db[4];
#pragma unroll
    for (int a = 0; a < 4; a++) db[a] = decb[a * 128 + u];

    float c[4] = {0.f, 0.f, 0.f, 0.f};

    float xn[4][4];
    if (kh == 0) {
#pragma unroll
        for (int b = 0; b < 4; b++) {
            const float* xr = g_xg + ((long)(b0 + tr + 8 * b) * 32 + 0) * 512;
#pragma unroll
            for (int a = 0; a < 4; a++) xn[b][a] = xr[a * 128 + u];
        }
    }

    int kbase = kh * 16;
    int pread = 0;
    for (int step = 0; step < 42; step++) {
        const float* ws = (step < 32) ? wse : wsd;
        const float* hsr = hs + pread * (32 * 128);

        unsigned long long acc2[4][4];
#pragma unroll
        for (int a = 0; a < 4; a++)
#pragma unroll
            for (int b = 0; b < 4; b++) acc2[a][b] = 0ull;

        for (int kk = kbase; kk < kbase + 16; kk++) {
            ulonglong2 w2v[4], h2v[4];
#pragma unroll
            for (int a = 0; a < 4; a++)
                w2v[a] = *reinterpret_cast<const ulonglong2*>(&ws[(a * 32 + tj) * WPAD + (kk << 2)]);
#pragma unroll
            for (int b = 0; b < 4; b++)
                h2v[b] = *reinterpret_cast<const ulonglong2*>(&hsr[(tr + 8 * b) * 128 + (kk << 2)]);
#pragma unroll
            for (int a = 0; a < 4; a++)
#pragma unroll
                for (int b = 0; b < 4; b++) {
                    fma2(acc2[a][b], w2v[a].x, h2v[b].x);
                    fma2(acc2[a][b], w2v[a].y, h2v[b].y);
                }
        }

        if (kh == 1) {
            float* dst = sred + (tid - 256) * SRSTRIDE;
#pragma unroll
            for (int a = 0; a < 4; a++)
#pragma unroll
                for (int b = 0; b < 4; b++) dst[a * 4 + b] = f2sum(acc2[a][b]);
        }
        __syncthreads();

        if (kh == 0) {
            const float* src = sred + tid * SRSTRIDE;
            unsigned woff = (unsigned)((1 - pread) * (32 * 128 * 4));
#pragma unroll
            for (int b = 0; b < 4; b++) {
                int rloc = tr + 8 * b;
                float gi = f2sum(acc2[0][b]) + src[0 * 4 + b] + xn[b][0];
                float gf = f2sum(acc2[1][b]) + src[1 * 4 + b] + xn[b][1];
                float gg = f2sum(acc2[2][b]) + src[2 * 4 + b] + xn[b][2];
                float go = f2sum(acc2[3][b]) + src[3 * 4 + b] + xn[b][3];
                float si = 1.f / (1.f + __expf(-gi));
                float sf = 1.f / (1.f + __expf(-gf));
                float so = 1.f / (1.f + __expf(-go));
                float tg = tanhf(gg);
                float cn = sf * c[b] + si * tg;
                c[b] = cn;
                float hn = so * tanhf(cn);
                if (step < 41) {
                    unsigned eoff = woff + (unsigned)(rloc * 128 + u) * 4u;
#pragma unroll
                    for (int r = 0; r < 4; r++)
                        asm volatile("st.shared::cluster.f32 [%0], %1;"
                                     :: "r"(rb[r] + eoff), "f"(hn) : "memory");
                }
                if (step >= 32) g_hdec[step - 32][(b0 + rloc) * 128 + u] = hn;
            }
        }

        if (step < 41) {
            asm volatile("barrier.cluster.arrive.aligned;" ::: "memory");
            if (kh == 0) {
                if (step + 1 < 32) {
#pragma unroll
                    for (int b = 0; b < 4; b++) {
                        const float* xr = g_xg + ((long)(b0 + tr + 8 * b) * 32 + (step + 1)) * 512;
#pragma unroll
                        for (int a = 0; a < 4; a++) xn[b][a] = xr[a * 128 + u];
                    }
                } else {
#pragma unroll
                    for (int b = 0; b < 4; b++)
#pragma unroll
                        for (int a = 0; a < 4; a++) xn[b][a] = db[a];
                }
            }
            asm volatile("barrier.cluster.wait.aligned;" ::: "memory");
            pread ^= 1;
        }
    }

    asm volatile("barrier.cluster.arrive.aligned;" ::: "memory");
    asm volatile("barrier.cluster.wait.aligned;" ::: "memory");
}

// ---------------- output head v2: f32x2, k-split 4, transposed w pairs ----------------
#define HPAD 130
__global__ void __launch_bounds__(256) head_kernel(
    const float* __restrict__ ow, const float* __restrict__ ob,
    float* __restrict__ out)
{
    extern __shared__ float hm[];
    float* hsm = hm;                  // 64 x HPAD
    float* wt2 = hsm + 64 * HPAD;     // 64 kk x 12 v x 2 floats (u64 pairs)
    float* red = wt2 + 64 * 12 * 2;   // 4 x 64 x 13

    int tid = threadIdx.x;
    int s = blockIdx.y, b0 = blockIdx.x * 64;
    for (int i = tid; i < 64 * 128; i += 256) {
        int r = i >> 7, k = i & 127;
        hsm[r * HPAD + k] = g_hdec[s][(b0 + r) * 128 + k];
    }
    for (int i = tid; i < 64 * 12; i += 256) {
        int kk = i / 12, v = i % 12;
        wt2[i * 2]     = ow[v * 128 + 2 * kk];
        wt2[i * 2 + 1] = ow[v * 128 + 2 * kk + 1];
    }
    __syncthreads();

    int b = tid & 63, kseg = tid >> 6;
    unsigned long long acc[12];
#pragma unroll
    for (int v = 0; v < 12; v++) acc[v] = 0ull;

    for (int kk = kseg * 16; kk < kseg * 16 + 16; kk++) {
        unsigned long long h2 = *(const unsigned long long*)&hsm[b * HPAD + (kk << 1)];
        const unsigned long long* wp = (const unsigned long long*)&wt2[kk * 24];
#pragma unroll
        for (int v = 0; v < 12; v++) fma2(acc[v], h2, wp[v]);
    }
    {
        float* dst = &red[(kseg * 64 + b) * 13];
#pragma unroll
        for (int v = 0; v < 12; v++) dst[v] = f2sum(acc[v]);
    }
    __syncthreads();

    for (int it = tid; it < 64 * 12; it += 256) {
        int b2 = it / 12, v = it % 12;
        float r = red[(0 * 64 + b2) * 13 + v] + red[(1 * 64 + b2) * 13 + v]
                + red[(2 * 64 + b2) * 13 + v] + red[(3 * 64 + b2) * 13 + v] + ob[v];
        out[(long)(b0 + b2) * 120 + s * 12 + v] = r;
    }
}

// ---------------- launcher ----------------
extern "C" void kernel_launch(void* const* d_in, const int* in_sizes, int n_in,
                              void* d_out, int out_size)
{
    const float* obs    = (const float*)d_in[0];
    const float* c1w    = (const float*)d_in[1];
    const float* c1b    = (const float*)d_in[2];
    const float* c2w    = (const float*)d_in[3];
    const float* c2b    = (const float*)d_in[4];
    const float* fc1w   = (const float*)d_in[5];
    const float* fc1b   = (const float*)d_in[6];
    const float* bn1g   = (const float*)d_in[7];
    const float* bn1b   = (const float*)d_in[8];
    const float* bn1m   = (const float*)d_in[9];
    const float* bn1v   = (const float*)d_in[10];
    const float* fc2w   = (const float*)d_in[11];
    const float* fc2b   = (const float*)d_in[12];
    const float* bn2g   = (const float*)d_in[13];
    const float* bn2b   = (const float*)d_in[14];
    const float* bn2m   = (const float*)d_in[15];
    const float* bn2v   = (const float*)d_in[16];
    const float* encwih = (const float*)d_in[17];
    const float* encwhh = (const float*)d_in[18];
    const float* encb   = (const float*)d_in[19];
    const float* decwih = (const float*)d_in[20];
    const float* decwhh = (const float*)d_in[21];
    const float* decb   = (const float*)d_in[22];
    const float* outw   = (const float*)d_in[23];
    const float* outb   = (const float*)d_in[24];
    float* out = (float*)d_out;

    const int fc_smem    = (128 * WPAD + 64 * WPAD + 64 * 128 * 2) * 4;
    const int xproj_smem = (128 * 64 + 128 * BPAD) * 4;
    const int lstm_smem  = (2 * 128 * WPAD + 2 * 32 * 128 + 256 * SRSTRIDE) * 4;
    const int head_smem  = (64 * HPAD + 64 * 12 * 2 + 4 * 64 * 13) * 4;
    cudaFuncSetAttribute(fc_kernel, cudaFuncAttributeMaxDynamicSharedMemorySize, fc_smem);
    cudaFuncSetAttribute(xproj_kernel, cudaFuncAttributeMaxDynamicSharedMemorySize, xproj_smem);
    cudaFuncSetAttribute(lstm_persistent, cudaFuncAttributeMaxDynamicSharedMemorySize, lstm_smem);
    cudaFuncSetAttribute(head_kernel, cudaFuncAttributeMaxDynamicSharedMemorySize, head_smem);

    cnn_kernel<<<CNN_GRID, 128>>>(obs, c1w, c1b, c2w, c2b);
    fc_kernel<<<FC_GRID, 256, fc_smem>>>(fc1w, fc1b, bn1g, bn1b, bn1m, bn1v,
                                         fc2w, fc2b, bn2g, bn2b, bn2m, bn2v);
    xproj_kernel<<<XP_GROUPS * 4, 512, xproj_smem>>>(encwih, encb);

    lstm_persistent<<<128, 512, lstm_smem>>>(encwhh, decwih, decwhh, decb);

    dim3 hgrid(16, 10);
    head_kernel<<<hgrid, 256, head_smem>>>(outw, outb, out);
}